// round 16
// baseline (speedup 1.0000x reference)
#include <cuda_runtime.h>
#include <math.h>
#include <stdint.h>

#define T_STEPS 1024
#define HID     256
#define NSPK    1251
#define F_IN    40

typedef unsigned long long ull;

// ---------------- device scratch ----------------
// Global self-flagging h exchange: layer->layer handoff + classifier feed.
// {h, epoch}; epoch == t+1 => valid. Zero at load; reinit re-zeroes at END.
__device__ float2 g_hx[3][T_STEPS][HID];   // 6 MB

// ---------------- helpers ----------------
__device__ __forceinline__ float poll_h_sleep(const float2* p, int epoch) {
    float h; int e;
    asm volatile("ld.relaxed.gpu.global.v2.b32 {%0,%1}, [%2];"
                 : "=f"(h), "=r"(e) : "l"(p));
    while (e != epoch) {
        __nanosleep(100);
        asm volatile("ld.relaxed.gpu.global.v2.b32 {%0,%1}, [%2];"
                     : "=f"(h), "=r"(e) : "l"(p));
    }
    return h;
}
__device__ __forceinline__ void pub_h(float2* p, float h, int epoch) {
    asm volatile("st.relaxed.gpu.global.v2.b32 [%0], {%1,%2};"
                 :: "l"(p), "f"(h), "r"(epoch));
}
__device__ __forceinline__ uint32_t smem_u32(const void* p) {
    uint32_t a;
    asm("{ .reg .u64 t; cvta.to.shared.u64 t, %1; cvt.u32.u64 %0, t; }" : "=r"(a) : "l"(p));
    return a;
}
__device__ __forceinline__ uint32_t mapa_u32(uint32_t addr, uint32_t rank) {
    uint32_t r; asm("mapa.shared::cluster.u32 %0, %1, %2;" : "=r"(r) : "r"(addr), "r"(rank));
    return r;
}
// poll a LOCAL smem {val, epoch} word (critical path: tight loop)
__device__ __forceinline__ float poll_local(uint32_t addr, int epoch) {
    uint32_t hb; int e;
    do {
        asm volatile("ld.volatile.shared.v2.b32 {%0,%1}, [%2];"
                     : "=r"(hb), "=r"(e) : "r"(addr));
    } while (e != epoch);
    return __uint_as_float(hb);
}
__device__ __forceinline__ void st_local2(uint32_t addr, float v, int epoch) {
    asm volatile("st.volatile.shared.v2.b32 [%0], {%1,%2};"
                 :: "r"(addr), "r"(__float_as_uint(v)), "r"(epoch) : "memory");
}
__device__ __forceinline__ int ld_local(uint32_t addr) {
    int v; asm volatile("ld.volatile.shared.b32 %0, [%1];" : "=r"(v) : "r"(addr));
    return v;
}
__device__ __forceinline__ void st_local(uint32_t addr, int v) {
    asm volatile("st.volatile.shared.b32 [%0], %1;" :: "r"(addr), "r"(v) : "memory");
}
__device__ __forceinline__ void ffma2(ull& acc, ull a, ull b) {
    asm("fma.rn.f32x2 %0, %1, %2, %0;" : "+l"(acc) : "l"(a), "l"(b));
}
__device__ __forceinline__ ull pack2(float a, float b) {
    ull v; asm("mov.b64 %0, {%1,%2};" : "=l"(v) : "f"(a), "f"(b)); return v;
}
__device__ __forceinline__ ull pack2u(uint32_t a, uint32_t b) {
    ull v; asm("mov.b64 %0, {%1,%2};" : "=l"(v) : "r"(a), "r"(b)); return v;
}
// HW tanh (MUFU.TANH)
__device__ __forceinline__ float tanh_hw(float x) {
    float r; asm("tanh.approx.f32 %0, %1;" : "=f"(r) : "f"(x)); return r;
}

// ---------------- reinit: zero global exchange buffer for the NEXT call ----------------
__global__ void reinit_epochs_kernel() {
    int i = blockIdx.x * blockDim.x + threadIdx.x;   // 1536*512 = 786432
    ((float2*)g_hx)[i] = make_float2(0.0f, 0.0f);
}

// ---------------- pipelined 3-layer LSTM ----------------
// grid 48 x 512, cluster (16,1,1) per layer; CTA rank c owns 16 units.
// CONSUMERS = warps 8-15 (hi-wid: arbiter priority). Warp u: units {2u,2u+1};
//   lane = hi*16 + gate*4 + k4. Per step: 64 threads stage h via LDS.128
//   quad-polls -> bar2 -> W_hh matvec (4 accs) -> xor-reduce -> +xg -> MUFU
//   tanh -> butterfly exchange (all lanes get i,f,g,o) -> redundant cst/hn in
//   every lane -> immediate 32-lane DSMEM push -> global publish.
// PRODUCERS = warps 0-7: stage upstream h / x -> bar1 -> W_ih matvec ->
//   backpressure (nanosleep) -> self-flagging xg word.
extern "C" __global__ void __launch_bounds__(512, 1)
lstm_pipeline_kernel(
    const float* __restrict__ x,
    const float* __restrict__ wih0, const float* __restrict__ whh0,
    const float* __restrict__ bih0, const float* __restrict__ bhh0,
    const float* __restrict__ wih1, const float* __restrict__ whh1,
    const float* __restrict__ bih1, const float* __restrict__ bhh1,
    const float* __restrict__ wih2, const float* __restrict__ whh2,
    const float* __restrict__ bih2, const float* __restrict__ bhh2)
{
    __shared__ float2 hx_s[2][HID];      // DSMEM push target {h, epoch}
    __shared__ float  h_s [2][HID];      // staged own-layer h(t-1)
    __shared__ float  hup_s[2][HID];     // upstream h / x staging (double-buffered)
    __shared__ float2 xg_s[2][68];       // {xg row val, epoch}, stride 17
    __shared__ int    cons_step_sto;     // consumer progress (volatile)

    const int tid  = threadIdx.x;
    const int l    = blockIdx.x >> 4;
    const int c    = blockIdx.x & 15;    // cluster rank
    const int lane = tid & 31;

    const float* whh = (l == 0) ? whh0 : (l == 1) ? whh1 : whh2;
    const float* wih = (l == 0) ? wih0 : (l == 1) ? wih1 : wih2;
    const float* bih = (l == 0) ? bih0 : (l == 1) ? bih1 : bih2;
    const float* bhh = (l == 0) ? bhh0 : (l == 1) ? bhh1 : bhh2;

    const uint32_t cons_step = smem_u32(&cons_step_sto);

    // ======== consumer state (tid >= 256) ========
    ull wh[32];
    uint32_t ra0 = 0, ra1 = 0, sa0 = 0, sa1 = 0, xga0 = 0, xga1 = 0, hsw = 0;
    int   my_unit = 0, k4c = 0, gate = 0;
    // ======== producer state (tid < 256) ========
    ull wi[32];
    float wx[10];
    float pbias = 0.0f;
    int prow = 0, pk4 = 0;
    uint32_t xw0 = 0, xw1 = 0;

    float nl_pre = 0.5f, nl_a = 0.5f, nl_b2 = 0.5f;   // sigmoid via tanh

    if (tid >= 256) {
        const int ctid = tid - 256;
        const int u    = ctid >> 5;
        const int hi   = lane >> 4;
        gate = (lane >> 2) & 3;
        k4c  = lane & 3;
        const int ul = 2 * u + hi;
        const int grow = gate * 256 + c * 16 + ul;
        #pragma unroll
        for (int j = 0; j < 16; j++) {
            const float* pr = whh + grow * HID + 16 * j + 4 * k4c;
            wh[2*j]   = *(const ull*)(pr);
            wh[2*j+1] = *(const ull*)(pr + 2);
        }
        my_unit = c * 16 + ul;
        if (gate == 2) { nl_pre = 1.0f; nl_a = 1.0f; nl_b2 = 0.0f; }  // tanh gate
        ra0 = mapa_u32(smem_u32(&hx_s[0][my_unit]), (uint32_t)(lane & 15));
        ra1 = mapa_u32(smem_u32(&hx_s[1][my_unit]), (uint32_t)(lane & 15));
        if (ctid < 64) {
            sa0 = smem_u32(&hx_s[0][4 * ctid]);      // 4 units per stager
            sa1 = smem_u32(&hx_s[1][4 * ctid]);
            hsw = smem_u32(&h_s[0][4 * ctid]);       // + b*HID*4 at use site
            *(float4*)&h_s[0][ctid * 4] = make_float4(0.f, 0.f, 0.f, 0.f);
        }
        const int xgi = gate * 17 + ul;
        xga0 = smem_u32(&xg_s[0][xgi]);
        xga1 = smem_u32(&xg_s[1][xgi]);
        if (ctid == 0) st_local(cons_step, -1);
    } else {
        prow = tid >> 2;                 // 0..63 gate row
        pk4  = tid & 3;
        const int pgrow = (prow >> 4) * 256 + c * 16 + (prow & 15);
        pbias = bih[pgrow] + bhh[pgrow];
        const int xgi = (prow >> 4) * 17 + (prow & 15);
        xw0 = smem_u32(&xg_s[0][xgi]);
        xw1 = smem_u32(&xg_s[1][xgi]);
        if (l == 0) {
            #pragma unroll
            for (int j = 0; j < 10; j++) wx[j] = wih[pgrow * F_IN + pk4 * 10 + j];
        } else {
            #pragma unroll
            for (int j = 0; j < 16; j++) {
                const float* pr = wih + pgrow * HID + 16 * j + 4 * pk4;
                wi[2*j]   = *(const ull*)(pr);
                wi[2*j+1] = *(const ull*)(pr + 2);
            }
        }
    }
    __syncthreads();
    asm volatile("barrier.cluster.arrive.aligned;" ::: "memory");
    asm volatile("barrier.cluster.wait.aligned;"   ::: "memory");

    if (tid >= 256) {
        // ==================== CONSUMER LOOP (warps 8-15) ====================
        const int ctid = tid - 256;
        float cst = 0.0f;                // replicated across the unit's 16 lanes
        for (int t = 0; t < T_STEPS; t++) {
            const int b = t & 1;

            // ---- staging: 64 threads x 4 units, quad-epoch poll ----
            if (ctid < 64 && t > 0) {
                uint32_t sa = b ? sa1 : sa0;
                uint32_t h0, e0, h1, e1, h2, e2, h3, e3;
                do {
                    asm volatile("ld.volatile.shared.v4.b32 {%0,%1,%2,%3}, [%4];"
                                 : "=r"(h0), "=r"(e0), "=r"(h1), "=r"(e1) : "r"(sa));
                    asm volatile("ld.volatile.shared.v4.b32 {%0,%1,%2,%3}, [%4];"
                                 : "=r"(h2), "=r"(e2), "=r"(h3), "=r"(e3) : "r"(sa + 16));
                } while (((e0 ^ t) | (e1 ^ t) | (e2 ^ t) | (e3 ^ t)) != 0u);
                asm volatile("st.shared.v4.b32 [%0], {%1,%2,%3,%4};"
                             :: "r"(hsw + (uint32_t)(b * HID * 4)),
                                "r"(h0), "r"(h1), "r"(h2), "r"(h3) : "memory");
            }
            asm volatile("bar.sync 2, 256;" ::: "memory");
            if (ctid == 0) st_local(cons_step, t);

            // xg (steady-state hit; miss overlaps matvec)
            float xg = poll_local(b ? xga1 : xga0, t + 1);

            // ---- W_hh matvec: 4 accumulators ----
            ull a0 = 0ULL, a1 = 0ULL, a2 = 0ULL, a3 = 0ULL;
            #pragma unroll
            for (int j = 0; j < 16; j += 2) {
                float4 hv0 = *(const float4*)&h_s[b][16 * j + 4 * k4c];
                float4 hv1 = *(const float4*)&h_s[b][16 * (j + 1) + 4 * k4c];
                ffma2(a0, wh[2*j],   pack2(hv0.x, hv0.y));
                ffma2(a1, wh[2*j+1], pack2(hv0.z, hv0.w));
                ffma2(a2, wh[2*j+2], pack2(hv1.x, hv1.y));
                ffma2(a3, wh[2*j+3], pack2(hv1.z, hv1.w));
            }
            float q0, q1, q2, q3, q4, q5, q6, q7;
            asm("mov.b64 {%0,%1}, %2;" : "=f"(q0), "=f"(q1) : "l"(a0));
            asm("mov.b64 {%0,%1}, %2;" : "=f"(q2), "=f"(q3) : "l"(a1));
            asm("mov.b64 {%0,%1}, %2;" : "=f"(q4), "=f"(q5) : "l"(a2));
            asm("mov.b64 {%0,%1}, %2;" : "=f"(q6), "=f"(q7) : "l"(a3));
            float p = ((q0 + q1) + (q2 + q3)) + ((q4 + q5) + (q6 + q7));
            p += __shfl_xor_sync(0xffffffffu, p, 1);
            p += __shfl_xor_sync(0xffffffffu, p, 2);
            p += xg;

            // per-lane nonlinearity (own gate), then butterfly exchange
            float val = fmaf(tanh_hw(nl_pre * p), nl_a, nl_b2);
            float vB = __shfl_xor_sync(0xffffffffu, val, 4);    // gate^1
            float vC = __shfl_xor_sync(0xffffffffu, val, 8);    // gate^2
            float vD = __shfl_xor_sync(0xffffffffu, vB, 8);     // gate^3

            // map to (i, f, g~, o) by own gate index
            float gi, gf, gg, go;
            if      (gate == 0) { gi = val; gf = vB;  gg = vC;  go = vD;  }
            else if (gate == 1) { gi = vB;  gf = val; gg = vD;  go = vC;  }
            else if (gate == 2) { gi = vC;  gf = vD;  gg = val; go = vB;  }
            else                { gi = vD;  gf = vC;  gg = vB;  go = val; }

            // redundant (bit-identical) cell update in all 16 lanes of the unit
            cst = gf * cst + gi * gg;
            float hn = go * tanh_hw(cst);

            // immediate DSMEM push {h, epoch=t+1} from all 32 lanes
            ull v = pack2u(__float_as_uint(hn), (uint32_t)(t + 1));
            uint32_t ra = ((t + 1) & 1) ? ra1 : ra0;
            asm volatile("st.shared::cluster.b64 [%0], %1;" :: "r"(ra), "l"(v) : "memory");
            if ((lane & 15) == 0) pub_h(&g_hx[l][t][my_unit], hn, t + 1);
        }
    } else {
        // ==================== PRODUCER LOOP (warps 0-7) ====================
        float xr = 0.0f;
        if (l == 0 && tid < F_IN) xr = x[(63 * T_STEPS + 0) * F_IN + tid];

        for (int t = 0; t < T_STEPS; t++) {
            const int b = t & 1;
            if (l == 0) {
                if (tid < F_IN) {
                    hup_s[b][tid] = xr;
                    if (t + 1 < T_STEPS)
                        xr = x[(63 * T_STEPS + (t + 1)) * F_IN + tid];  // prefetch
                }
            } else {
                hup_s[b][tid] = poll_h_sleep(&g_hx[l-1][t][tid], t + 1);
            }
            asm volatile("bar.sync 1, 256;" ::: "memory");

            float p = 0.0f;
            if (l == 0) {
                #pragma unroll
                for (int j = 0; j < 10; j++) p = fmaf(wx[j], hup_s[b][pk4 * 10 + j], p);
            } else {
                ull a0 = 0ULL, a1 = 0ULL;
                #pragma unroll
                for (int j = 0; j < 16; j++) {
                    float4 hv = *(const float4*)&hup_s[b][16 * j + 4 * pk4];
                    ffma2(a0, wi[2*j],   pack2(hv.x, hv.y));
                    ffma2(a1, wi[2*j+1], pack2(hv.z, hv.w));
                }
                float q0, q1, q2, q3;
                asm("mov.b64 {%0,%1}, %2;" : "=f"(q0), "=f"(q1) : "l"(a0));
                asm("mov.b64 {%0,%1}, %2;" : "=f"(q2), "=f"(q3) : "l"(a1));
                p = (q0 + q1) + (q2 + q3);
            }
            p += __shfl_xor_sync(0xffffffffu, p, 1);
            p += __shfl_xor_sync(0xffffffffu, p, 2);

            if (pk4 == 0) {
                if (t >= 2) {
                    while (ld_local(cons_step) < t - 1) { __nanosleep(64); }
                }
                st_local2(b ? xw1 : xw0, p + pbias, t + 1);
            }
        }
    }

    asm volatile("barrier.cluster.arrive.aligned;" ::: "memory");
    asm volatile("barrier.cluster.wait.aligned;"   ::: "memory");
}

// ---------------- classifier: logits = h2 @ W_lin^T + b, log_softmax ----------------
__global__ __launch_bounds__(512, 1) void classifier_kernel(
    const float* __restrict__ wlin,
    const float* __restrict__ blin,
    float* __restrict__ out)
{
    __shared__ float lg[4 * NSPK];
    __shared__ float hsm[4 * HID];
    __shared__ float rbuf[16];

    const int b    = blockIdx.x;
    const int t0   = b * 4;
    const int tid  = threadIdx.x;
    const int lane = tid & 31;
    const int wd   = tid >> 5;

    for (int i = tid; i < 4 * HID; i += 512)
        hsm[i] = g_hx[2][t0 + (i >> 8)][i & 255].x;
    __syncthreads();

    float hr[4][8];
    #pragma unroll
    for (int t = 0; t < 4; t++)
        #pragma unroll
        for (int j = 0; j < 8; j++) hr[t][j] = hsm[t * HID + lane * 8 + j];

    for (int o = wd; o < NSPK; o += 16) {
        const float4* wp = (const float4*)(wlin + o * HID + lane * 8);
        float4 w0 = wp[0], w1 = wp[1];
        float wv[8] = {w0.x, w0.y, w0.z, w0.w, w1.x, w1.y, w1.z, w1.w};
        float a0 = 0.f, a1 = 0.f, a2 = 0.f, a3 = 0.f;
        #pragma unroll
        for (int j = 0; j < 8; j++) {
            float wj = wv[j];
            a0 = fmaf(wj, hr[0][j], a0);
            a1 = fmaf(wj, hr[1][j], a1);
            a2 = fmaf(wj, hr[2][j], a2);
            a3 = fmaf(wj, hr[3][j], a3);
        }
        #pragma unroll
        for (int off = 16; off > 0; off >>= 1) {
            a0 += __shfl_xor_sync(0xffffffffu, a0, off);
            a1 += __shfl_xor_sync(0xffffffffu, a1, off);
            a2 += __shfl_xor_sync(0xffffffffu, a2, off);
            a3 += __shfl_xor_sync(0xffffffffu, a3, off);
        }
        if (lane == 0) {
            float bb = blin[o];
            lg[0 * NSPK + o] = a0 + bb;
            lg[1 * NSPK + o] = a1 + bb;
            lg[2 * NSPK + o] = a2 + bb;
            lg[3 * NSPK + o] = a3 + bb;
        }
    }
    __syncthreads();

    for (int t = 0; t < 4; t++) {
        float m = -1e30f;
        for (int o = tid; o < NSPK; o += 512) m = fmaxf(m, lg[t * NSPK + o]);
        #pragma unroll
        for (int off = 16; off > 0; off >>= 1)
            m = fmaxf(m, __shfl_xor_sync(0xffffffffu, m, off));
        if (lane == 0) rbuf[wd] = m;
        __syncthreads();
        float mm = rbuf[0];
        #pragma unroll
        for (int i = 1; i < 16; i++) mm = fmaxf(mm, rbuf[i]);
        __syncthreads();

        float s = 0.0f;
        for (int o = tid; o < NSPK; o += 512) s += __expf(lg[t * NSPK + o] - mm);
        #pragma unroll
        for (int off = 16; off > 0; off >>= 1)
            s += __shfl_xor_sync(0xffffffffu, s, off);
        if (lane == 0) rbuf[wd] = s;
        __syncthreads();
        float ss = 0.0f;
        #pragma unroll
        for (int i = 0; i < 16; i++) ss += rbuf[i];
        float lse = mm + logf(ss);

        for (int o = tid; o < NSPK; o += 512)
            out[(size_t)(t0 + t) * NSPK + o] = lg[t * NSPK + o] - lse;
        __syncthreads();
    }
}

// ---------------- launch ----------------
extern "C" void kernel_launch(void* const* d_in, const int* in_sizes, int n_in,
                              void* d_out, int out_size)
{
    const float* x    = (const float*)d_in[0];
    const float* wih0 = (const float*)d_in[1];
    const float* whh0 = (const float*)d_in[2];
    const float* bih0 = (const float*)d_in[3];
    const float* bhh0 = (const float*)d_in[4];
    const float* wih1 = (const float*)d_in[5];
    const float* whh1 = (const float*)d_in[6];
    const float* bih1 = (const float*)d_in[7];
    const float* bhh1 = (const float*)d_in[8];
    const float* wih2 = (const float*)d_in[9];
    const float* whh2 = (const float*)d_in[10];
    const float* bih2 = (const float*)d_in[11];
    const float* bhh2 = (const float*)d_in[12];
    const float* wlin = (const float*)d_in[13];
    const float* blin = (const float*)d_in[14];
    float* out = (float*)d_out;

    cudaFuncSetAttribute(lstm_pipeline_kernel,
                         cudaFuncAttributeNonPortableClusterSizeAllowed, 1);

    cudaLaunchConfig_t cfg = {};
    cfg.gridDim  = dim3(48, 1, 1);
    cfg.blockDim = dim3(512, 1, 1);
    cfg.dynamicSmemBytes = 0;
    cfg.stream = 0;
    cudaLaunchAttribute attrs[1];
    attrs[0].id = cudaLaunchAttributeClusterDimension;
    attrs[0].val.clusterDim.x = 16;
    attrs[0].val.clusterDim.y = 1;
    attrs[0].val.clusterDim.z = 1;
    cfg.attrs = attrs;
    cfg.numAttrs = 1;

    cudaLaunchKernelEx(&cfg, lstm_pipeline_kernel, x,
                       wih0, whh0, bih0, bhh0,
                       wih1, whh1, bih1, bhh1,
                       wih2, whh2, bih2, bhh2);

    classifier_kernel<<<256, 512>>>(wlin, blin, out);
    reinit_epochs_kernel<<<1536, 512>>>();
}

// round 17
// speedup vs baseline: 1.0388x; 1.0388x over previous
#include <cuda_runtime.h>
#include <math.h>
#include <stdint.h>

#define T_STEPS 1024
#define HID     256
#define NSPK    1251
#define F_IN    40

typedef unsigned long long ull;

// ---------------- device scratch ----------------
// Global self-flagging h exchange: layer->layer handoff + classifier feed.
// {h, epoch}; epoch == t+1 => valid. Zero at load; reinit re-zeroes at END.
__device__ float2 g_hx[3][T_STEPS][HID];   // 6 MB

// ---------------- helpers ----------------
__device__ __forceinline__ float poll_h_sleep(const float2* p, int epoch) {
    float h; int e;
    asm volatile("ld.relaxed.gpu.global.v2.b32 {%0,%1}, [%2];"
                 : "=f"(h), "=r"(e) : "l"(p));
    while (e != epoch) {
        __nanosleep(100);
        asm volatile("ld.relaxed.gpu.global.v2.b32 {%0,%1}, [%2];"
                     : "=f"(h), "=r"(e) : "l"(p));
    }
    return h;
}
__device__ __forceinline__ void pub_h(float2* p, float h, int epoch) {
    asm volatile("st.relaxed.gpu.global.v2.b32 [%0], {%1,%2};"
                 :: "l"(p), "f"(h), "r"(epoch));
}
__device__ __forceinline__ uint32_t smem_u32(const void* p) {
    uint32_t a;
    asm("{ .reg .u64 t; cvta.to.shared.u64 t, %1; cvt.u32.u64 %0, t; }" : "=r"(a) : "l"(p));
    return a;
}
__device__ __forceinline__ uint32_t mapa_u32(uint32_t addr, uint32_t rank) {
    uint32_t r; asm("mapa.shared::cluster.u32 %0, %1, %2;" : "=r"(r) : "r"(addr), "r"(rank));
    return r;
}
// poll a LOCAL smem {val, epoch} word (critical path: tight loop)
__device__ __forceinline__ float poll_local(uint32_t addr, int epoch) {
    uint32_t hb; int e;
    do {
        asm volatile("ld.volatile.shared.v2.b32 {%0,%1}, [%2];"
                     : "=r"(hb), "=r"(e) : "r"(addr));
    } while (e != epoch);
    return __uint_as_float(hb);
}
__device__ __forceinline__ void st_local2(uint32_t addr, float v, int epoch) {
    asm volatile("st.volatile.shared.v2.b32 [%0], {%1,%2};"
                 :: "r"(addr), "r"(__float_as_uint(v)), "r"(epoch) : "memory");
}
__device__ __forceinline__ int ld_local(uint32_t addr) {
    int v; asm volatile("ld.volatile.shared.b32 %0, [%1];" : "=r"(v) : "r"(addr));
    return v;
}
__device__ __forceinline__ void st_local(uint32_t addr, int v) {
    asm volatile("st.volatile.shared.b32 [%0], %1;" :: "r"(addr), "r"(v) : "memory");
}
__device__ __forceinline__ void ffma2(ull& acc, ull a, ull b) {
    asm("fma.rn.f32x2 %0, %1, %2, %0;" : "+l"(acc) : "l"(a), "l"(b));
}
__device__ __forceinline__ ull pack2(float a, float b) {
    ull v; asm("mov.b64 %0, {%1,%2};" : "=l"(v) : "f"(a), "f"(b)); return v;
}
__device__ __forceinline__ ull pack2u(uint32_t a, uint32_t b) {
    ull v; asm("mov.b64 %0, {%1,%2};" : "=l"(v) : "r"(a), "r"(b)); return v;
}
// HW tanh (MUFU.TANH)
__device__ __forceinline__ float tanh_hw(float x) {
    float r; asm("tanh.approx.f32 %0, %1;" : "=f"(r) : "f"(x)); return r;
}

// ---------------- reinit: zero global exchange buffer for the NEXT call ----------------
__global__ void reinit_epochs_kernel() {
    int i = blockIdx.x * blockDim.x + threadIdx.x;   // 1536*512 = 786432
    ((float2*)g_hx)[i] = make_float2(0.0f, 0.0f);
}

// ---------------- pipelined 3-layer LSTM: decoupled consumer/producer ----------------
// grid 48 x 512, cluster (16,1,1) per layer; CTA rank c owns 16 units.
// Consumers (warps 0-7, bar 2): poll own local hx word -> STS h_s[b] -> bar2 ->
//   xg poll (steady-state hit) -> W_hh matvec (4 accs) -> kc reduce ->
//   MUFU-tanh per-lane gate -> butterfly exchange (all lanes get i,f,g,o) ->
//   redundant per-lane cst/hn -> immediate 32-lane DSMEM push -> global publish.
// Producers (warps 8-15, bar 1): stage upstream h / x -> bar1 -> W_ih matvec
//   -> backpressure (nanosleep) -> self-flagging xg word.
extern "C" __global__ void __launch_bounds__(512, 1)
lstm_pipeline_kernel(
    const float* __restrict__ x,
    const float* __restrict__ wih0, const float* __restrict__ whh0,
    const float* __restrict__ bih0, const float* __restrict__ bhh0,
    const float* __restrict__ wih1, const float* __restrict__ whh1,
    const float* __restrict__ bih1, const float* __restrict__ bhh1,
    const float* __restrict__ wih2, const float* __restrict__ whh2,
    const float* __restrict__ bih2, const float* __restrict__ bhh2)
{
    __shared__ float2 hx_s[2][HID];      // DSMEM push target {h, epoch}
    __shared__ float  h_s [2][HID];      // staged own-layer h(t-1)
    __shared__ float  hup_s[2][HID];     // upstream h / x staging (double-buffered)
    __shared__ float2 xg_s[2][68];       // {xg row val, epoch}, stride 17
    __shared__ int    cons_step_sto;     // consumer progress (volatile)

    const int tid  = threadIdx.x;
    const int l    = blockIdx.x >> 4;
    const int c    = blockIdx.x & 15;    // cluster rank
    const int lane = tid & 31;

    const float* whh = (l == 0) ? whh0 : (l == 1) ? whh1 : whh2;
    const float* wih = (l == 0) ? wih0 : (l == 1) ? wih1 : wih2;
    const float* bih = (l == 0) ? bih0 : (l == 1) ? bih1 : bih2;
    const float* bhh = (l == 0) ? bhh0 : (l == 1) ? bhh1 : bhh2;

    const uint32_t cons_step = smem_u32(&cons_step_sto);

    // ======== consumer state (tid < 256) ========
    ull wh[32];
    uint32_t ra0 = 0, ra1 = 0, pa0 = 0, pa1 = 0, xga0 = 0, xga1 = 0;
    int   my_unit = 0, k4c = 0, gate = 0;
    // ======== producer state (tid >= 256) ========
    ull wi[32];
    float wx[10];
    float pbias = 0.0f;
    int prow = 0, pk4 = 0;
    uint32_t xw0 = 0, xw1 = 0;

    float nl_pre = 0.5f, nl_a = 0.5f, nl_b2 = 0.5f;   // sigmoid via tanh

    if (tid < 256) {
        const int u  = tid >> 5;
        const int hi = lane >> 4;
        gate = (lane >> 2) & 3;
        k4c  = lane & 3;
        const int ul = 2 * u + hi;
        const int grow = gate * 256 + c * 16 + ul;
        #pragma unroll
        for (int j = 0; j < 16; j++) {
            const float* pr = whh + grow * HID + 16 * j + 4 * k4c;
            wh[2*j]   = *(const ull*)(pr);
            wh[2*j+1] = *(const ull*)(pr + 2);
        }
        my_unit = c * 16 + ul;
        if (gate == 2) { nl_pre = 1.0f; nl_a = 1.0f; nl_b2 = 0.0f; }  // tanh gate
        ra0 = mapa_u32(smem_u32(&hx_s[0][my_unit]), (uint32_t)(lane & 15));
        ra1 = mapa_u32(smem_u32(&hx_s[1][my_unit]), (uint32_t)(lane & 15));
        pa0 = smem_u32(&hx_s[0][tid]);
        pa1 = smem_u32(&hx_s[1][tid]);
        const int xgi = gate * 17 + ul;
        xga0 = smem_u32(&xg_s[0][xgi]);
        xga1 = smem_u32(&xg_s[1][xgi]);
        if (tid < 64) *(float4*)&h_s[0][tid * 4] = make_float4(0.f, 0.f, 0.f, 0.f);
        if (tid == 0) st_local(cons_step, -1);
    } else {
        const int thr = tid - 256;
        prow = thr >> 2;                 // 0..63 gate row
        pk4  = thr & 3;
        const int pgrow = (prow >> 4) * 256 + c * 16 + (prow & 15);
        pbias = bih[pgrow] + bhh[pgrow];
        const int xgi = (prow >> 4) * 17 + (prow & 15);
        xw0 = smem_u32(&xg_s[0][xgi]);
        xw1 = smem_u32(&xg_s[1][xgi]);
        if (l == 0) {
            #pragma unroll
            for (int j = 0; j < 10; j++) wx[j] = wih[pgrow * F_IN + pk4 * 10 + j];
        } else {
            #pragma unroll
            for (int j = 0; j < 16; j++) {
                const float* pr = wih + pgrow * HID + 16 * j + 4 * pk4;
                wi[2*j]   = *(const ull*)(pr);
                wi[2*j+1] = *(const ull*)(pr + 2);
            }
        }
    }
    __syncthreads();
    asm volatile("barrier.cluster.arrive.aligned;" ::: "memory");
    asm volatile("barrier.cluster.wait.aligned;"   ::: "memory");

    if (tid < 256) {
        // ==================== CONSUMER LOOP (warps 0-7) ====================
        float cst = 0.0f;                // replicated across the unit's 16 lanes
        for (int t = 0; t < T_STEPS; t++) {
            const int b = t & 1;
            if (t > 0) h_s[b][tid] = poll_local(b ? pa1 : pa0, t);
            asm volatile("bar.sync 2, 256;" ::: "memory");
            if (tid == 0) st_local(cons_step, t);

            // xg hoisted before matvec (steady-state hit; miss overlaps FMAs)
            float xg = poll_local(b ? xga1 : xga0, t + 1);

            // ---- W_hh matvec: 4 accumulators (halved RAW chain) ----
            ull a0 = 0ULL, a1 = 0ULL, a2 = 0ULL, a3 = 0ULL;
            #pragma unroll
            for (int j = 0; j < 16; j += 2) {
                float4 hv0 = *(const float4*)&h_s[b][16 * j + 4 * k4c];
                float4 hv1 = *(const float4*)&h_s[b][16 * (j + 1) + 4 * k4c];
                ffma2(a0, wh[2*j],   pack2(hv0.x, hv0.y));
                ffma2(a1, wh[2*j+1], pack2(hv0.z, hv0.w));
                ffma2(a2, wh[2*j+2], pack2(hv1.x, hv1.y));
                ffma2(a3, wh[2*j+3], pack2(hv1.z, hv1.w));
            }
            float q0, q1, q2, q3, q4, q5, q6, q7;
            asm("mov.b64 {%0,%1}, %2;" : "=f"(q0), "=f"(q1) : "l"(a0));
            asm("mov.b64 {%0,%1}, %2;" : "=f"(q2), "=f"(q3) : "l"(a1));
            asm("mov.b64 {%0,%1}, %2;" : "=f"(q4), "=f"(q5) : "l"(a2));
            asm("mov.b64 {%0,%1}, %2;" : "=f"(q6), "=f"(q7) : "l"(a3));
            float p = ((q0 + q1) + (q2 + q3)) + ((q4 + q5) + (q6 + q7));
            p += __shfl_xor_sync(0xffffffffu, p, 1);
            p += __shfl_xor_sync(0xffffffffu, p, 2);
            p += xg;

            // per-lane nonlinearity (own gate), then butterfly exchange
            float val = fmaf(tanh_hw(nl_pre * p), nl_a, nl_b2);
            float vB = __shfl_xor_sync(0xffffffffu, val, 4);    // gate^1
            float vC = __shfl_xor_sync(0xffffffffu, val, 8);    // gate^2
            float vD = __shfl_xor_sync(0xffffffffu, vB, 8);     // gate^3

            // map to (i, f, g~, o) by own gate index
            float gi, gf, gg, go;
            if      (gate == 0) { gi = val; gf = vB;  gg = vC;  go = vD;  }
            else if (gate == 1) { gi = vB;  gf = val; gg = vD;  go = vC;  }
            else if (gate == 2) { gi = vC;  gf = vD;  gg = val; go = vB;  }
            else                { gi = vD;  gf = vC;  gg = vB;  go = val; }

            // redundant (bit-identical) cell update in all 16 lanes of the unit
            cst = gf * cst + gi * gg;
            float hn = go * tanh_hw(cst);

            // immediate DSMEM push {h, epoch=t+1} from all 32 lanes
            ull v = pack2u(__float_as_uint(hn), (uint32_t)(t + 1));
            uint32_t ra = ((t + 1) & 1) ? ra1 : ra0;
            asm volatile("st.shared::cluster.b64 [%0], %1;" :: "r"(ra), "l"(v) : "memory");
            if ((lane & 15) == 0) pub_h(&g_hx[l][t][my_unit], hn, t + 1);
        }
    } else {
        // ==================== PRODUCER LOOP (warps 8-15) ====================
        const int thr = tid - 256;
        float xr = 0.0f;
        if (l == 0 && thr < F_IN) xr = x[(63 * T_STEPS + 0) * F_IN + thr];

        for (int t = 0; t < T_STEPS; t++) {
            const int b = t & 1;
            if (l == 0) {
                if (thr < F_IN) {
                    hup_s[b][thr] = xr;
                    if (t + 1 < T_STEPS)
                        xr = x[(63 * T_STEPS + (t + 1)) * F_IN + thr];  // prefetch
                }
            } else {
                hup_s[b][thr] = poll_h_sleep(&g_hx[l-1][t][thr], t + 1);
            }
            asm volatile("bar.sync 1, 256;" ::: "memory");

            float p = 0.0f;
            if (l == 0) {
                #pragma unroll
                for (int j = 0; j < 10; j++) p = fmaf(wx[j], hup_s[b][pk4 * 10 + j], p);
            } else {
                ull a0 = 0ULL, a1 = 0ULL;
                #pragma unroll
                for (int j = 0; j < 16; j++) {
                    float4 hv = *(const float4*)&hup_s[b][16 * j + 4 * pk4];
                    ffma2(a0, wi[2*j],   pack2(hv.x, hv.y));
                    ffma2(a1, wi[2*j+1], pack2(hv.z, hv.w));
                }
                float q0, q1, q2, q3;
                asm("mov.b64 {%0,%1}, %2;" : "=f"(q0), "=f"(q1) : "l"(a0));
                asm("mov.b64 {%0,%1}, %2;" : "=f"(q2), "=f"(q3) : "l"(a1));
                p = (q0 + q1) + (q2 + q3);
            }
            p += __shfl_xor_sync(0xffffffffu, p, 1);
            p += __shfl_xor_sync(0xffffffffu, p, 2);

            if (pk4 == 0) {
                if (t >= 2) {
                    while (ld_local(cons_step) < t - 1) { __nanosleep(64); }
                }
                st_local2(b ? xw1 : xw0, p + pbias, t + 1);
            }
        }
    }

    asm volatile("barrier.cluster.arrive.aligned;" ::: "memory");
    asm volatile("barrier.cluster.wait.aligned;"   ::: "memory");
}

// ---------------- classifier: logits = h2 @ W_lin^T + b, log_softmax ----------------
__global__ __launch_bounds__(512, 1) void classifier_kernel(
    const float* __restrict__ wlin,
    const float* __restrict__ blin,
    float* __restrict__ out)
{
    __shared__ float lg[4 * NSPK];
    __shared__ float hsm[4 * HID];
    __shared__ float rbuf[16];

    const int b    = blockIdx.x;
    const int t0   = b * 4;
    const int tid  = threadIdx.x;
    const int lane = tid & 31;
    const int wd   = tid >> 5;

    for (int i = tid; i < 4 * HID; i += 512)
        hsm[i] = g_hx[2][t0 + (i >> 8)][i & 255].x;
    __syncthreads();

    float hr[4][8];
    #pragma unroll
    for (int t = 0; t < 4; t++)
        #pragma unroll
        for (int j = 0; j < 8; j++) hr[t][j] = hsm[t * HID + lane * 8 + j];

    for (int o = wd; o < NSPK; o += 16) {
        const float4* wp = (const float4*)(wlin + o * HID + lane * 8);
        float4 w0 = wp[0], w1 = wp[1];
        float wv[8] = {w0.x, w0.y, w0.z, w0.w, w1.x, w1.y, w1.z, w1.w};
        float a0 = 0.f, a1 = 0.f, a2 = 0.f, a3 = 0.f;
        #pragma unroll
        for (int j = 0; j < 8; j++) {
            float wj = wv[j];
            a0 = fmaf(wj, hr[0][j], a0);
            a1 = fmaf(wj, hr[1][j], a1);
            a2 = fmaf(wj, hr[2][j], a2);
            a3 = fmaf(wj, hr[3][j], a3);
        }
        #pragma unroll
        for (int off = 16; off > 0; off >>= 1) {
            a0 += __shfl_xor_sync(0xffffffffu, a0, off);
            a1 += __shfl_xor_sync(0xffffffffu, a1, off);
            a2 += __shfl_xor_sync(0xffffffffu, a2, off);
            a3 += __shfl_xor_sync(0xffffffffu, a3, off);
        }
        if (lane == 0) {
            float bb = blin[o];
            lg[0 * NSPK + o] = a0 + bb;
            lg[1 * NSPK + o] = a1 + bb;
            lg[2 * NSPK + o] = a2 + bb;
            lg[3 * NSPK + o] = a3 + bb;
        }
    }
    __syncthreads();

    for (int t = 0; t < 4; t++) {
        float m = -1e30f;
        for (int o = tid; o < NSPK; o += 512) m = fmaxf(m, lg[t * NSPK + o]);
        #pragma unroll
        for (int off = 16; off > 0; off >>= 1)
            m = fmaxf(m, __shfl_xor_sync(0xffffffffu, m, off));
        if (lane == 0) rbuf[wd] = m;
        __syncthreads();
        float mm = rbuf[0];
        #pragma unroll
        for (int i = 1; i < 16; i++) mm = fmaxf(mm, rbuf[i]);
        __syncthreads();

        float s = 0.0f;
        for (int o = tid; o < NSPK; o += 512) s += __expf(lg[t * NSPK + o] - mm);
        #pragma unroll
        for (int off = 16; off > 0; off >>= 1)
            s += __shfl_xor_sync(0xffffffffu, s, off);
        if (lane == 0) rbuf[wd] = s;
        __syncthreads();
        float ss = 0.0f;
        #pragma unroll
        for (int i = 0; i < 16; i++) ss += rbuf[i];
        float lse = mm + logf(ss);

        for (int o = tid; o < NSPK; o += 512)
            out[(size_t)(t0 + t) * NSPK + o] = lg[t * NSPK + o] - lse;
        __syncthreads();
    }
}

// ---------------- launch ----------------
extern "C" void kernel_launch(void* const* d_in, const int* in_sizes, int n_in,
                              void* d_out, int out_size)
{
    const float* x    = (const float*)d_in[0];
    const float* wih0 = (const float*)d_in[1];
    const float* whh0 = (const float*)d_in[2];
    const float* bih0 = (const float*)d_in[3];
    const float* bhh0 = (const float*)d_in[4];
    const float* wih1 = (const float*)d_in[5];
    const float* whh1 = (const float*)d_in[6];
    const float* bih1 = (const float*)d_in[7];
    const float* bhh1 = (const float*)d_in[8];
    const float* wih2 = (const float*)d_in[9];
    const float* whh2 = (const float*)d_in[10];
    const float* bih2 = (const float*)d_in[11];
    const float* bhh2 = (const float*)d_in[12];
    const float* wlin = (const float*)d_in[13];
    const float* blin = (const float*)d_in[14];
    float* out = (float*)d_out;

    cudaFuncSetAttribute(lstm_pipeline_kernel,
                         cudaFuncAttributeNonPortableClusterSizeAllowed, 1);

    cudaLaunchConfig_t cfg = {};
    cfg.gridDim  = dim3(48, 1, 1);
    cfg.blockDim = dim3(512, 1, 1);
    cfg.dynamicSmemBytes = 0;
    cfg.stream = 0;
    cudaLaunchAttribute attrs[1];
    attrs[0].id = cudaLaunchAttributeClusterDimension;
    attrs[0].val.clusterDim.x = 16;
    attrs[0].val.clusterDim.y = 1;
    attrs[0].val.clusterDim.z = 1;
    cfg.attrs = attrs;
    cfg.numAttrs = 1;

    cudaLaunchKernelEx(&cfg, lstm_pipeline_kernel, x,
                       wih0, whh0, bih0, bhh0,
                       wih1, whh1, bih1, bhh1,
                       wih2, whh2, bih2, bhh2);

    classifier_kernel<<<256, 512>>>(wlin, blin, out);
    reinit_epochs_kernel<<<1536, 512>>>();
}